// round 14
// baseline (speedup 1.0000x reference)
#include <cuda_runtime.h>
#include <math.h>

#define L   12288
#define BB  8
#define NI  24                    // i-chunks
#define CHUNK (L / NI)            // 512 rows per chunk
#define THREADS 256
#define WARPS (THREADS / 32)
#define GX  (L / THREADS)         // 48 column-groups (1 col/thread)
#define RB  8                     // row batch
#define NB  (CHUNK / RB)          // 64 batches per chunk
#define DEPTH 4                   // cp.async ring depth (NB % DEPTH == 0)

// Scratch (static device globals — allocation-free)
__device__ float g_part[NI][BB][L];   // partial candidate sums (~9.4 MB)
__device__ float g_cnt[NI][L];        // partial counts
__device__ float g_bpart[GX][BB];     // per-column-group squared-diff sums
__device__ unsigned g_tk_col[GX];     // per-column-group tickets (self-reset)
__device__ unsigned g_tk_fin;         // final ticket (self-reset)

__device__ __forceinline__ void cp_async16(void* s, const void* g) {
    unsigned sa = (unsigned)__cvta_generic_to_shared(s);
    asm volatile("cp.async.cg.shared.global [%0], [%1], 16;" :: "r"(sa), "l"(g));
}
__device__ __forceinline__ void cp_commit() {
    asm volatile("cp.async.commit_group;" ::: "memory");
}
template <int N>
__device__ __forceinline__ void cp_wait() {
    asm volatile("cp.async.wait_group %0;" :: "n"(N) : "memory");
}

// ---------------------------------------------------------------------------
// Single fused kernel.
// Main phase: partial cand[b][j] / cnt[j] per (column-group, chunk) block.
// Finish phase (last chunk-block per column group, via ticket): candidates,
// diff = p - sim @ cand, per-b squared sums; final ticket block: norms,
// valid mask, mean -> out.
// ---------------------------------------------------------------------------
__global__ __launch_bounds__(THREADS, 4)
void fused_kernel(const float* __restrict__ predicts,
                  const float* __restrict__ adj,
                  const int* __restrict__ mask,
                  const float* __restrict__ sim,
                  float* __restrict__ out) {
    __shared__ float sp[CHUNK][BB];                  // 16 KB predicts tile
    __shared__ int   smask[WARPS][DEPTH][RB][32];    // 32 KB warp-private rings

    const int t     = threadIdx.x;
    const int l     = t & 31;
    const int w     = t >> 5;
    const int jbase = blockIdx.x * THREADS;
    const int j     = jbase + t;                     // this thread's column
    const int chunk = blockIdx.y;
    const int i0    = chunk * CHUNK;

    // cp.async mapping (per warp, per batch: 8 rows x 128B)
    const int r0  = l >> 3;
    const int sg  = (l & 7) * 4;
    const int* gw = mask + (size_t)i0 * L + jbase + w * 32 + sg;

    float acc[BB];
    int   cnt = 0;
#pragma unroll
    for (int b = 0; b < BB; ++b) acc[b] = 0.f;

    // predicts tile transposed (CHUNK = 2 * THREADS)
    for (int s = t; s < CHUNK; s += THREADS)
#pragma unroll
        for (int b = 0; b < BB; ++b)
            sp[s][b] = predicts[b * L + i0 + s];

    // ---- prologue: mask batches 0..DEPTH-1 ----
#pragma unroll
    for (int q = 0; q < DEPTH; ++q) {
        cp_async16(&smask[w][q][r0][sg],     gw + (size_t)(q * RB + r0) * L);
        cp_async16(&smask[w][q][r0 + 4][sg], gw + (size_t)(q * RB + r0 + 4) * L);
        cp_commit();
    }

    __syncthreads();          // sp visible block-wide
    cp_wait<3>();
    __syncwarp();

    const float* ap = adj + (size_t)i0 * L + j;
    float a_cur[RB], a_next[RB];
#pragma unroll
    for (int r = 0; r < RB; ++r) {
        const int m = smask[w][0][r][l];
        cnt += m;
        a_cur[r] = m ? __ldcs(ap + (size_t)r * L) : 0.0f;
    }

    // ---- steady state ----
    for (int kb = 0; kb < NB; kb += DEPTH) {
#pragma unroll
        for (int u = 0; u < DEPTH; ++u) {
            const int k = kb + u;

            cp_wait<2>();
            __syncwarp();

            if (k + 1 < NB) {
                const float* apn = ap + (size_t)RB * L;
#pragma unroll
                for (int r = 0; r < RB; ++r) {
                    const int m = smask[w][(u + 1) % DEPTH][r][l];
                    cnt += m;
                    a_next[r] = m ? __ldcs(apn + (size_t)r * L) : 0.0f;
                }
            }

            const int ii = k * RB;
#pragma unroll
            for (int r = 0; r < RB; ++r) {
                const float a = a_cur[r];
                if (a != 0.0f) {
                    const float4 lo = *(const float4*)&sp[ii + r][0];
                    const float4 hi = *(const float4*)&sp[ii + r][4];
                    acc[0] = fmaf(lo.x, a, acc[0]);
                    acc[1] = fmaf(lo.y, a, acc[1]);
                    acc[2] = fmaf(lo.z, a, acc[2]);
                    acc[3] = fmaf(lo.w, a, acc[3]);
                    acc[4] = fmaf(hi.x, a, acc[4]);
                    acc[5] = fmaf(hi.y, a, acc[5]);
                    acc[6] = fmaf(hi.z, a, acc[6]);
                    acc[7] = fmaf(hi.w, a, acc[7]);
                }
            }

            if (k + DEPTH < NB) {
                const size_t roff = (size_t)((k + DEPTH) * RB) * L;
                cp_async16(&smask[w][u][r0][sg],     gw + roff + (size_t)r0 * L);
                cp_async16(&smask[w][u][r0 + 4][sg], gw + roff + (size_t)(r0 + 4) * L);
            }
            cp_commit();

            ap += (size_t)RB * L;
#pragma unroll
            for (int r = 0; r < RB; ++r) a_cur[r] = a_next[r];
        }
    }

    g_cnt[chunk][j] = (float)cnt;
#pragma unroll
    for (int b = 0; b < BB; ++b)
        g_part[chunk][b][j] = acc[b];

    // ======== finish phase (ticketed) ========
    __shared__ bool sdone;
    __threadfence();
    if (t == 0) {
        unsigned n = atomicAdd(&g_tk_col[blockIdx.x], 1u);
        sdone = (n == NI - 1);
    }
    __syncthreads();
    if (!sdone) return;

    // This block is last for column group blockIdx.x: finish its 256 columns.
    __shared__ float ssim[BB * BB];
    __shared__ float scand[BB][33];
    __shared__ float sadd[32], sinv[32];

    if (t < BB * BB) ssim[t] = sim[t];

    const int fb = w;        // this thread's batch index b (warp id)
    float ssq = 0.f;

    for (int jc = 0; jc < THREADS / 32; ++jc) {
        const int jj = jbase + jc * 32 + l;

        if (fb == 0) {
            float cf = 0.f;
#pragma unroll
            for (int c = 0; c < NI; ++c) cf += g_cnt[c][jj];
            const float mjj = mask[(size_t)jj * (L + 1)] ? 1.f : 0.f;
            const float add = 1.f - mjj;
            sadd[l] = add;
            sinv[l] = 1.f / (cf + add);
        }

        float accp = 0.f;
#pragma unroll
        for (int c = 0; c < NI; ++c) accp += g_part[c][fb][jj];
        const float p = predicts[fb * L + jj];
        __syncthreads();

        const float cand = (accp + p * sadd[l]) * sinv[l];
        scand[fb][l] = cand;
        __syncthreads();

        float d = p;
#pragma unroll
        for (int k = 0; k < BB; ++k) d -= ssim[fb * BB + k] * scand[k][l];
        ssq += d * d;
        __syncthreads();     // protect sadd/scand before next jc overwrites
    }

#pragma unroll
    for (int o = 16; o > 0; o >>= 1) ssq += __shfl_down_sync(0xffffffffu, ssq, o);
    if (l == 0) g_bpart[blockIdx.x][fb] = ssq;
    if (t == 0) g_tk_col[blockIdx.x] = 0;   // reset for next replay

    // ---- final global ticket ----
    __shared__ bool sfin;
    __threadfence();
    if (t == 0) {
        unsigned m2 = atomicAdd(&g_tk_fin, 1u);
        sfin = (m2 == GX - 1);
    }
    __syncthreads();
    if (!sfin) return;

    __shared__ float norms[BB];
    if (w < BB) {
        float s = g_bpart[l][w] + (l < GX - 32 ? g_bpart[l + 32][w] : 0.f);
#pragma unroll
        for (int o = 16; o > 0; o >>= 1) s += __shfl_down_sync(0xffffffffu, s, o);
        if (l == 0) norms[w] = sqrtf(s);
    }
    __syncthreads();

    if (t == 0) {
        float total = 0.f, c2 = 0.f;
        for (int bb = 0; bb < BB; ++bb) {
            float rs = 0.f;
            for (int k = 0; k < BB; ++k) rs += ssim[bb * BB + k];
            if (rs != 0.f) { c2 += 1.f; total += norms[bb]; }
        }
        out[0] = (c2 == 0.f) ? 0.f : total / fmaxf(c2, 1.f);
        g_tk_fin = 0;                        // reset for next replay
    }
}

// ---------------------------------------------------------------------------
extern "C" void kernel_launch(void* const* d_in, const int* in_sizes, int n_in,
                              void* d_out, int out_size) {
    (void)in_sizes; (void)n_in; (void)out_size;
    const float* predicts = (const float*)d_in[0];   // [8, L]
    const float* sim      = (const float*)d_in[1];   // [8, 8]
    const float* adj      = (const float*)d_in[2];   // [L, L]
    const int*   mask     = (const int*)d_in[3];     // [L, L] bool->int32
    float* out = (float*)d_out;

    dim3 g1(GX, NI);
    fused_kernel<<<g1, THREADS>>>(predicts, adj, mask, sim, out);
}